// round 9
// baseline (speedup 1.0000x reference)
#include <cuda_runtime.h>
#include <cstdint>

#define RES 256
#define N_TOTAL (8 * 65536)
#define NBLK 1024
#define PPB 512                 // points per block (2 per thread)
#define THREADS 256
#define SLABS 8
#define SLAB_FLOATS (RES * RES * 32)        // 2,097,152 floats = 8MB per z-slab
#define SHARE_FLOATS (SLAB_FLOATS / NBLK)   // 2048 floats per block per slab

__device__ __forceinline__ float sel4(float4 v, int o) {
    float r = (o == 1) ? v.y : v.x;
    r = (o == 2) ? v.z : r;
    r = (o == 3) ? v.w : r;
    return r;
}

// Trilinear sample of one point; coords from smem, result -> out (streaming store).
__device__ __forceinline__ void gather_point(const float* __restrict__ sc3,
                                             const float* __restrict__ vol,
                                             float* __restrict__ outp)
{
    float gx = sc3[0], gy = sc3[1], gz = sc3[2];

    float ix = fmaf(gx, 256.0f, 127.5f);
    float iy = fmaf(gy, 256.0f, 127.5f);
    float iz = fmaf(gz, 256.0f, 127.5f);

    float fx0 = floorf(ix), fy0 = floorf(iy), fz0 = floorf(iz);
    float tx = ix - fx0, ty = iy - fy0, tz = iz - fz0;

    int x0 = (int)fx0, y0 = (int)fy0, z0 = (int)fz0;
    int x1 = x0 + 1,   y1 = y0 + 1,   z1 = z0 + 1;

    bool vx0 = (x0 >= 0) & (x0 < RES);
    bool vx1 = (x1 >= 0) & (x1 < RES);
    bool vy0 = (y0 >= 0) & (y0 < RES);
    bool vy1 = (y1 >= 0) & (y1 < RES);
    bool vz0 = (z0 >= 0) & (z0 < RES);
    bool vz1 = (z1 >= 0) & (z1 < RES);

    int cx0 = min(max(x0, 0), RES - 1);
    int cx1 = min(max(x1, 0), RES - 1);
    int cy0 = min(max(y0, 0), RES - 1);
    int cy1 = min(max(y1, 0), RES - 1);
    int cz0 = min(max(z0, 0), RES - 1);
    int cz1 = min(max(z1, 0), RES - 1);

    long pz0 = (long)cz0 * (RES * RES);
    long pz1 = (long)cz1 * (RES * RES);
    long r00 = pz0 + cy0 * RES;
    long r01 = pz0 + cy1 * RES;
    long r10 = pz1 + cy0 * RES;
    long r11 = pz1 + cy1 * RES;

    int base = cx0 & ~3;          // 16B aligned, always in-bounds
    int ao = cx0 - base;
    int d1 = cx1 - base;
    int bo = min(d1, 3);
    bool need_extra = (d1 == 4);

    float4 q00 = __ldg((const float4*)(vol + r00 + base));
    float4 q01 = __ldg((const float4*)(vol + r01 + base));
    float4 q10 = __ldg((const float4*)(vol + r10 + base));
    float4 q11 = __ldg((const float4*)(vol + r11 + base));

    float e00 = 0.f, e01 = 0.f, e10 = 0.f, e11 = 0.f;
    if (need_extra) {
        e00 = __ldg(vol + r00 + cx1);
        e01 = __ldg(vol + r01 + cx1);
        e10 = __ldg(vol + r10 + cx1);
        e11 = __ldg(vol + r11 + cx1);
    }

    float a00 = sel4(q00, ao), a01 = sel4(q01, ao);
    float a10 = sel4(q10, ao), a11 = sel4(q11, ao);
    float b00 = need_extra ? e00 : sel4(q00, bo);
    float b01 = need_extra ? e01 : sel4(q01, bo);
    float b10 = need_extra ? e10 : sel4(q10, bo);
    float b11 = need_extra ? e11 : sel4(q11, bo);

    a00 = (vz0 & vy0 & vx0) ? a00 : 0.0f;
    b00 = (vz0 & vy0 & vx1) ? b00 : 0.0f;
    a01 = (vz0 & vy1 & vx0) ? a01 : 0.0f;
    b01 = (vz0 & vy1 & vx1) ? b01 : 0.0f;
    a10 = (vz1 & vy0 & vx0) ? a10 : 0.0f;
    b10 = (vz1 & vy0 & vx1) ? b10 : 0.0f;
    a11 = (vz1 & vy1 & vx0) ? a11 : 0.0f;
    b11 = (vz1 & vy1 & vx1) ? b11 : 0.0f;

    float c00 = fmaf(tx, b00 - a00, a00);
    float c01 = fmaf(tx, b01 - a01, a01);
    float c10 = fmaf(tx, b10 - a10, a10);
    float c11 = fmaf(tx, b11 - a11, a11);

    float c0 = fmaf(ty, c01 - c00, c00);
    float c1 = fmaf(ty, c11 - c10, c10);
    float c  = fmaf(tz, c1 - c0, c0);

    float r = 100.0f * c;
    asm volatile("st.global.cs.f32 [%0], %1;" :: "l"(outp), "f"(r) : "memory");
}

__global__ __launch_bounds__(THREADS) void volume_sample_kernel(
    const float* __restrict__ x,
    const float* __restrict__ vol,
    float* __restrict__ out)
{
    __shared__ float          sc[PPB * 3];     // 6KB coords
    __shared__ unsigned short order[PPB];      // 1KB sorted point order
    __shared__ int            cnt[SLABS];
    __shared__ int            ofs[SLABS];
    __shared__ int            startofs[SLABS + 1];

    int b = blockIdx.x;
    int t = threadIdx.x;

    // ---- Phase A: load coords, bucket-sort points by z-slab, stream slab 0 ----
    const float* xb = x + (size_t)b * PPB * 3;
    #pragma unroll
    for (int j = 0; j < 6; j++)
        sc[t + j * THREADS] = __ldcs(xb + t + j * THREADS);
    if (t < SLABS) cnt[t] = 0;
    __syncthreads();

    int slab0, slab1;
    {
        float gz0 = sc[(t) * 3 + 2];
        float gz1 = sc[(t + 256) * 3 + 2];
        int z0 = (int)floorf(fmaf(gz0, 256.0f, 127.5f));
        int z1 = (int)floorf(fmaf(gz1, 256.0f, 127.5f));
        slab0 = min(max(z0, 0), 255) >> 5;
        slab1 = min(max(z1, 0), 255) >> 5;
        atomicAdd(&cnt[slab0], 1);
        atomicAdd(&cnt[slab1], 1);
    }
    __syncthreads();
    if (t == 0) {
        int run = 0;
        #pragma unroll
        for (int s = 0; s < SLABS; s++) { startofs[s] = run; ofs[s] = run; run += cnt[s]; }
        startofs[SLABS] = run;
    }
    __syncthreads();
    {
        int p0 = atomicAdd(&ofs[slab0], 1);
        order[p0] = (unsigned short)t;
        int p1 = atomicAdd(&ofs[slab1], 1);
        order[p1] = (unsigned short)(t + 256);
    }

    // stream slab 0 share (2048 floats/block) before gathers begin
    {
        const float4* p = (const float4*)(vol + (size_t)b * SHARE_FLOATS) + t;
        float4 a = __ldg(p);
        float4 d = __ldg(p + 256);
        asm volatile("" :: "f"(a.x), "f"(a.y), "f"(a.z), "f"(a.w),
                           "f"(d.x), "f"(d.y), "f"(d.z), "f"(d.w));
    }
    __syncthreads();

    // ---- Phase B: 8 z-chunks; gather slab c while streaming slab c+1 ----
    int w = t >> 5, l = t & 31;
    float* outb = out + (size_t)b * PPB;

    for (int c = 0; c < SLABS; c++) {
        float4 sa, sd;
        const float4* sp = nullptr;
        if (c < SLABS - 1) {
            sp = (const float4*)(vol + (size_t)(c + 1) * SLAB_FLOATS
                                     + (size_t)b * SHARE_FLOATS) + t;
            sa = __ldg(sp);          // issue stream loads first (in flight
            sd = __ldg(sp + 256);    //  while gathers below execute)
        }

        int s0 = startofs[c], s1 = startofs[c + 1];
        // spread entries across all 8 warps: e = s0 + w + 8*l covers 0..255 uniquely
        for (int e = s0 + w + 8 * l; e < s1; e += 256) {
            int p = order[e];
            gather_point(sc + p * 3, vol, outb + p);
        }

        if (c < SLABS - 1) {
            asm volatile("" :: "f"(sa.x), "f"(sa.y), "f"(sa.z), "f"(sa.w),
                               "f"(sd.x), "f"(sd.y), "f"(sd.z), "f"(sd.w));
        }
        __syncthreads();
    }
}

extern "C" void kernel_launch(void* const* d_in, const int* in_sizes, int n_in,
                              void* d_out, int out_size)
{
    const float* x   = (const float*)d_in[0];  // [8, 65536, 3] f32
    const float* vol = (const float*)d_in[1];  // [256,256,256] f32
    float* out = (float*)d_out;                // [8, 65536] f32

    volume_sample_kernel<<<NBLK, THREADS>>>(x, vol, out);
}

// round 10
// speedup vs baseline: 1.5253x; 1.5253x over previous
#include <cuda_runtime.h>
#include <cstdint>

#define RES 256
#define N_TOTAL (8 * 65536)
#define THREADS 256
#define NBLK (N_TOTAL / THREADS)          // 2048
#define SHARE_F4 2048                      // float4s per block share (32KB)

__device__ __forceinline__ uint64_t evict_last_policy() {
    uint64_t pol;
    asm("createpolicy.fractional.L2::evict_last.b64 %0, 1.0;" : "=l"(pol));
    return pol;
}

__device__ __forceinline__ float4 ldg_keep4(const float* p, uint64_t pol) {
    float4 v;
    asm volatile("ld.global.nc.L2::cache_hint.v4.f32 {%0,%1,%2,%3}, [%4], %5;"
                 : "=f"(v.x), "=f"(v.y), "=f"(v.z), "=f"(v.w)
                 : "l"(p), "l"(pol));
    return v;
}

__device__ __forceinline__ float ldg_keep(const float* p, uint64_t pol) {
    float v;
    asm volatile("ld.global.nc.L2::cache_hint.f32 %0, [%1], %2;"
                 : "=f"(v) : "l"(p), "l"(pol));
    return v;
}

__device__ __forceinline__ void consume4(float4 v) {
    asm volatile("" :: "f"(v.x), "f"(v.y), "f"(v.z), "f"(v.w));
}

__device__ __forceinline__ float sel4(float4 v, int o) {
    float r = (o == 1) ? v.y : v.x;
    r = (o == 2) ? v.z : r;
    r = (o == 3) ? v.w : r;
    return r;
}

__global__ __launch_bounds__(THREADS) void volume_sample_kernel(
    const float* __restrict__ x,
    const float* __restrict__ vol,
    float* __restrict__ out)
{
    int i = blockIdx.x * blockDim.x + threadIdx.x;

    uint64_t pol = evict_last_policy();

    // ---- Phase 1: sequential stream of this block's 32KB volume share ----
    // 2048 blocks x 32KB = entire 64MB volume, fully coalesced, evict-last.
    {
        const float4* p = (const float4*)vol
                        + (size_t)blockIdx.x * SHARE_F4 + threadIdx.x;
        float4 s0 = ldg_keep4((const float*)(p + 0 * THREADS), pol);
        float4 s1 = ldg_keep4((const float*)(p + 1 * THREADS), pol);
        float4 s2 = ldg_keep4((const float*)(p + 2 * THREADS), pol);
        float4 s3 = ldg_keep4((const float*)(p + 3 * THREADS), pol);
        float4 s4 = ldg_keep4((const float*)(p + 4 * THREADS), pol);
        float4 s5 = ldg_keep4((const float*)(p + 5 * THREADS), pol);
        float4 s6 = ldg_keep4((const float*)(p + 6 * THREADS), pol);
        float4 s7 = ldg_keep4((const float*)(p + 7 * THREADS), pol);
        consume4(s0); consume4(s1); consume4(s2); consume4(s3);
        consume4(s4); consume4(s5); consume4(s6); consume4(s7);
    }
    __syncthreads();   // block-wide barrier: gathers start only after stream lands

    // ---- Phase 2: trilinear gather (round-4 proven body) ----
    float gx = __ldcs(x + 3 * i + 0);
    float gy = __ldcs(x + 3 * i + 1);
    float gz = __ldcs(x + 3 * i + 2);

    float ix = fmaf(gx, 256.0f, 127.5f);
    float iy = fmaf(gy, 256.0f, 127.5f);
    float iz = fmaf(gz, 256.0f, 127.5f);

    float fx0 = floorf(ix), fy0 = floorf(iy), fz0 = floorf(iz);
    float tx = ix - fx0, ty = iy - fy0, tz = iz - fz0;

    int x0 = (int)fx0, y0 = (int)fy0, z0 = (int)fz0;
    int x1 = x0 + 1,   y1 = y0 + 1,   z1 = z0 + 1;

    bool vx0 = (x0 >= 0) & (x0 < RES);
    bool vx1 = (x1 >= 0) & (x1 < RES);
    bool vy0 = (y0 >= 0) & (y0 < RES);
    bool vy1 = (y1 >= 0) & (y1 < RES);
    bool vz0 = (z0 >= 0) & (z0 < RES);
    bool vz1 = (z1 >= 0) & (z1 < RES);

    int cx0 = min(max(x0, 0), RES - 1);
    int cx1 = min(max(x1, 0), RES - 1);
    int cy0 = min(max(y0, 0), RES - 1);
    int cy1 = min(max(y1, 0), RES - 1);
    int cz0 = min(max(z0, 0), RES - 1);
    int cz1 = min(max(z1, 0), RES - 1);

    long pz0 = (long)cz0 * (RES * RES);
    long pz1 = (long)cz1 * (RES * RES);
    long r00 = pz0 + cy0 * RES;
    long r01 = pz0 + cy1 * RES;
    long r10 = pz1 + cy0 * RES;
    long r11 = pz1 + cy1 * RES;

    int base = cx0 & ~3;          // 16B-aligned; base+3 <= 255 always
    int ao = cx0 - base;
    int d1 = cx1 - base;
    int bo = min(d1, 3);
    bool need_extra = (d1 == 4);  // ~25% of lanes

    float4 q00 = ldg_keep4(vol + r00 + base, pol);
    float4 q01 = ldg_keep4(vol + r01 + base, pol);
    float4 q10 = ldg_keep4(vol + r10 + base, pol);
    float4 q11 = ldg_keep4(vol + r11 + base, pol);

    float e00 = 0.f, e01 = 0.f, e10 = 0.f, e11 = 0.f;
    if (need_extra) {
        e00 = ldg_keep(vol + r00 + cx1, pol);
        e01 = ldg_keep(vol + r01 + cx1, pol);
        e10 = ldg_keep(vol + r10 + cx1, pol);
        e11 = ldg_keep(vol + r11 + cx1, pol);
    }

    float a00 = sel4(q00, ao), a01 = sel4(q01, ao);
    float a10 = sel4(q10, ao), a11 = sel4(q11, ao);
    float b00 = need_extra ? e00 : sel4(q00, bo);
    float b01 = need_extra ? e01 : sel4(q01, bo);
    float b10 = need_extra ? e10 : sel4(q10, bo);
    float b11 = need_extra ? e11 : sel4(q11, bo);

    a00 = (vz0 & vy0 & vx0) ? a00 : 0.0f;
    b00 = (vz0 & vy0 & vx1) ? b00 : 0.0f;
    a01 = (vz0 & vy1 & vx0) ? a01 : 0.0f;
    b01 = (vz0 & vy1 & vx1) ? b01 : 0.0f;
    a10 = (vz1 & vy0 & vx0) ? a10 : 0.0f;
    b10 = (vz1 & vy0 & vx1) ? b10 : 0.0f;
    a11 = (vz1 & vy1 & vx0) ? a11 : 0.0f;
    b11 = (vz1 & vy1 & vx1) ? b11 : 0.0f;

    float c00 = fmaf(tx, b00 - a00, a00);
    float c01 = fmaf(tx, b01 - a01, a01);
    float c10 = fmaf(tx, b10 - a10, a10);
    float c11 = fmaf(tx, b11 - a11, a11);

    float c0 = fmaf(ty, c01 - c00, c00);
    float c1 = fmaf(ty, c11 - c10, c10);
    float c  = fmaf(tz, c1 - c0, c0);

    float r = 100.0f * c;
    asm volatile("st.global.cs.f32 [%0], %1;" :: "l"(out + i), "f"(r) : "memory");
}

extern "C" void kernel_launch(void* const* d_in, const int* in_sizes, int n_in,
                              void* d_out, int out_size)
{
    const float* x   = (const float*)d_in[0];  // [8, 65536, 3] f32
    const float* vol = (const float*)d_in[1];  // [256,256,256] f32
    float* out = (float*)d_out;                // [8, 65536] f32

    volume_sample_kernel<<<NBLK, THREADS>>>(x, vol, out);
}